// round 11
// baseline (speedup 1.0000x reference)
#include <cuda_runtime.h>
#include <cstdint>

#define GS     16
#define NPAIR  136          // 16*17/2 lower-triangular pairs
#define NACC   152          // 136 pair sums + 16 channel sums
#define GROUPS 32
#define BATCH  32
#define HW     3136         // 56*56
#define HW4    784          // HW/4 (float4 units)
#define CH     512

typedef unsigned long long ull;

static __device__ float d_acc[GROUPS][NACC];   // pair sums + channel sums
static __device__ float d_Linv[GROUPS][NPAIR]; // packed lower-triangular Linv
static __device__ float d_bias[CH];            // Linv @ mean, per channel

// ---- packed f32x2 helpers (Blackwell) --------------------------------------
__device__ __forceinline__ void fma2(ull& d, ull a, ull b) {
    asm("fma.rn.f32x2 %0, %1, %2, %0;" : "+l"(d) : "l"(a), "l"(b));
}
__device__ __forceinline__ void add2(ull& d, ull a) {
    asm("add.rn.f32x2 %0, %0, %1;" : "+l"(d) : "l"(a));
}
__device__ __forceinline__ float unpack_add(ull v) {
    float lo, hi;
    asm("mov.b64 {%0,%1}, %2;" : "=f"(lo), "=f"(hi) : "l"(v));
    return lo + hi;
}
__device__ __forceinline__ ull pack2(float lo, float hi) {
    ull r;
    asm("mov.b64 %0, {%1,%2};" : "=l"(r) : "f"(lo), "f"(hi));
    return r;
}

struct V2 { ull a, b; };   // one float4 = two packed f32x2 halves

__device__ __forceinline__ V2 ld_v2(const float4* p) {
    const float4 f = __ldg(p);
    V2 v;
    v.a = pack2(f.x, f.y);
    v.b = pack2(f.z, f.w);
    return v;
}

// ---------------------------------------------------------------------------
__global__ void zero_kernel() {
    int i = blockIdx.x * blockDim.x + threadIdx.x;
    if (i < GROUPS * NACC) ((float*)d_acc)[i] = 0.f;
}

// ---------------------------------------------------------------------------
// Stats v9: role-per-BLOCK, apply-like pure streaming. No smem, no barriers.
// grid = 1024 tiles x 4 roles, 256 threads:
//   role 0: diag H0 (36 pairs + 8 sums), reads ch 0-7,  all positions
//   role 1: diag H1 (36 pairs + 8 sums), reads ch 8-15, all positions
//   role 2: cross 8x8 (64 pairs), reads all 16 ch, positions [0, 392)
//   role 3: cross 8x8 (64 pairs), reads all 16 ch, positions [392, 784)
// Total DRAM = 2x input (410 MB). Each block: load-burst (MLP 8-16) -> fma2.
__global__ void __launch_bounds__(256) stats_kernel(const float* __restrict__ x) {
    const int role = blockIdx.x & 3;
    const int bg   = blockIdx.x >> 2;
    const int g = bg & 31;
    const int b = bg >> 5;
    const float4* in = (const float4*)(x + ((size_t)b * CH + (size_t)g * GS) * HW);

    const int tid  = threadIdx.x;
    const int lane = tid & 31;
    const int wid  = tid >> 5;

    if (role < 2) {
        // ---------------- diagonal half: 36 pairs + 8 sums ------------------
        const int co = role * 8;
        ull acc[36], sum[8];
#pragma unroll
        for (int k = 0; k < 36; k++) acc[k] = 0ull;
#pragma unroll
        for (int k = 0; k < 8; k++) sum[k] = 0ull;

        for (int pos = tid; pos < HW4; pos += 256) {
            V2 v[8];
#pragma unroll
            for (int c = 0; c < 8; c++) v[c] = ld_v2(in + (size_t)(co + c) * HW4 + pos);
#pragma unroll
            for (int i = 0; i < 8; i++) {
#pragma unroll
                for (int j = 0; j <= i; j++) {
                    const int k = i * (i + 1) / 2 + j;
                    fma2(acc[k], v[i].a, v[j].a);
                    fma2(acc[k], v[i].b, v[j].b);
                }
                add2(sum[i], v[i].a);
                add2(sum[i], v[i].b);
            }
        }

        float r[44];
#pragma unroll
        for (int k = 0; k < 36; k++) r[k] = unpack_add(acc[k]);
#pragma unroll
        for (int k = 0; k < 8; k++)  r[36 + k] = unpack_add(sum[k]);
#pragma unroll
        for (int k = 0; k < 44; k++) {
#pragma unroll
            for (int off = 16; off > 0; off >>= 1)
                r[k] += __shfl_xor_sync(0xffffffffu, r[k], off);
        }

        __shared__ float red[8][44];
        if (lane == 0) {
#pragma unroll
            for (int k = 0; k < 44; k++) red[wid][k] = r[k];
        }
        __syncthreads();
        if (tid < 44) {
            float s = 0.f;
#pragma unroll
            for (int w = 0; w < 8; w++) s += red[w][tid];
            if (tid < 36) {
                // decode packed lower-tri index within the 8x8 half
                int i = 0;
                while ((i + 1) * (i + 2) / 2 <= tid) i++;
                const int j = tid - i * (i + 1) / 2;
                const int gi = co + i, gj = co + j;
                atomicAdd(&d_acc[g][gi * (gi + 1) / 2 + gj], s);
            } else {
                atomicAdd(&d_acc[g][NPAIR + co + (tid - 36)], s);
            }
        }
    } else {
        // ---------------- cross 8x8 over half the positions -----------------
        const int beg = (role - 2) * (HW4 / 2);
        const int end = beg + (HW4 / 2);
        ull acc[64];
#pragma unroll
        for (int k = 0; k < 64; k++) acc[k] = 0ull;

        for (int pos = beg + tid; pos < end; pos += 256) {
            V2 u[8], w[8];
#pragma unroll
            for (int c = 0; c < 8; c++) {
                w[c] = ld_v2(in + (size_t)c * HW4 + pos);
                u[c] = ld_v2(in + (size_t)(8 + c) * HW4 + pos);
            }
#pragma unroll
            for (int i = 0; i < 8; i++)
#pragma unroll
                for (int j = 0; j < 8; j++) {
                    const int k = i * 8 + j;
                    fma2(acc[k], u[i].a, w[j].a);
                    fma2(acc[k], u[i].b, w[j].b);
                }
        }

        float r[64];
#pragma unroll
        for (int k = 0; k < 64; k++) r[k] = unpack_add(acc[k]);
#pragma unroll
        for (int k = 0; k < 64; k++) {
#pragma unroll
            for (int off = 16; off > 0; off >>= 1)
                r[k] += __shfl_xor_sync(0xffffffffu, r[k], off);
        }

        __shared__ float red[8][64];
        if (lane == 0) {
#pragma unroll
            for (int k = 0; k < 64; k++) red[wid][k] = r[k];
        }
        __syncthreads();
        if (tid < 64) {
            float s = 0.f;
#pragma unroll
            for (int w = 0; w < 8; w++) s += red[w][tid];
            const int i = tid >> 3, j = tid & 7;
            const int gi = 8 + i;
            atomicAdd(&d_acc[g][gi * (gi + 1) / 2 + j], s);
        }
    }
}

// ---------------------------------------------------------------------------
// Solve: one block per group, 16 threads, everything in shared memory, fp64.
__global__ void __launch_bounds__(16) solve_kernel() {
    const int g = blockIdx.x;
    const int t = threadIdx.x;
    __shared__ double P[GS][GS + 1];
    __shared__ double L[GS][GS + 1];
    __shared__ double V[GS][GS + 1];
    __shared__ double m[GS];

    const double Nd   = (double)BATCH * (double)HW;
    const double EPSd = 1e-3;
    const unsigned MASK = 0xffffu;

    m[t] = (double)d_acc[g][NPAIR + t] / Nd;
    __syncwarp(MASK);

    for (int j = 0; j < GS; j++) {
        const int i_ = t > j ? t : j, j_ = t > j ? j : t;
        double c = (double)d_acc[g][i_ * (i_ + 1) / 2 + j_] / Nd - m[t] * m[j];
        c *= (1.0 - EPSd);
        if (t == j) c += EPSd;
        P[t][j] = c;
    }
    __syncwarp(MASK);

    for (int j = 0; j < GS; j++) {
        if (t == j) {
            double s = P[j][j];
            for (int k = 0; k < j; k++) s -= L[j][k] * L[j][k];
            L[j][j] = sqrt(s);
        }
        __syncwarp(MASK);
        if (t > j) {
            double s = P[t][j];
            for (int k = 0; k < j; k++) s -= L[t][k] * L[j][k];
            L[t][j] = s / L[j][j];
        }
        __syncwarp(MASK);
    }

    V[t][t] = 1.0 / L[t][t];
    for (int i = t + 1; i < GS; i++) {
        double s = 0.0;
        for (int k = t; k < i; k++) s += L[i][k] * V[k][t];
        V[i][t] = -s / L[i][i];
    }
    __syncwarp(MASK);

    double bsum = 0.0;
    for (int j = 0; j <= t; j++) {
        d_Linv[g][t * (t + 1) / 2 + j] = (float)V[t][j];
        bsum += V[t][j] * m[j];
    }
    d_bias[g * GS + t] = (float)bsum;
}

// ---------------------------------------------------------------------------
// Apply (unchanged, proven ~65us / 69% DRAM):
// out_i = sum_{j<=i} Linv_ij * x_j - bias_i, float4, streaming stores.
__global__ void __launch_bounds__(256, 2) apply_kernel(const float* __restrict__ x,
                                                       float* __restrict__ out) {
    const int g = blockIdx.x & 31;
    const int b = blockIdx.x >> 5;

    __shared__ float Ls[NPAIR];
    __shared__ float bs[GS];
    if (threadIdx.x < NPAIR) Ls[threadIdx.x] = d_Linv[g][threadIdx.x];
    if (threadIdx.x < GS)    bs[threadIdx.x] = d_bias[g * GS + threadIdx.x];
    __syncthreads();

    const size_t off = ((size_t)b * CH + (size_t)g * GS) * HW;
    const float4* in = (const float4*)(x + off);
    float4*       op = (float4*)(out + off);

    for (int pos = threadIdx.x; pos < HW4; pos += 256) {
        float4 v[GS];
#pragma unroll
        for (int c = 0; c < GS; c++) v[c] = in[(size_t)c * HW4 + pos];
#pragma unroll
        for (int i = 0; i < GS; i++) {
            const float bias = bs[i];
            float4 a;
            a.x = -bias; a.y = -bias; a.z = -bias; a.w = -bias;
#pragma unroll
            for (int j = 0; j <= i; j++) {
                const float f = Ls[i * (i + 1) / 2 + j];
                a.x = fmaf(f, v[j].x, a.x);
                a.y = fmaf(f, v[j].y, a.y);
                a.z = fmaf(f, v[j].z, a.z);
                a.w = fmaf(f, v[j].w, a.w);
            }
            __stcs(&op[(size_t)i * HW4 + pos], a);
        }
    }
}

// ---------------------------------------------------------------------------
extern "C" void kernel_launch(void* const* d_in, const int* in_sizes, int n_in,
                              void* d_out, int out_size) {
    const float* x   = (const float*)d_in[0];
    float*       out = (float*)d_out;

    zero_kernel<<<(GROUPS * NACC + 255) / 256, 256>>>();
    stats_kernel<<<GROUPS * BATCH * 4, 256>>>(x);
    solve_kernel<<<GROUPS, 16>>>();
    apply_kernel<<<GROUPS * BATCH, 256>>>(x, out);
}

// round 12
// speedup vs baseline: 1.0030x; 1.0030x over previous
#include <cuda_runtime.h>
#include <cstdint>

#define GS     16
#define NPAIR  136          // 16*17/2 lower-triangular pairs
#define NACC   152          // 136 pair sums + 16 channel sums
#define GROUPS 32
#define BATCH  32
#define HW     3136         // 56*56
#define HW4    784          // HW/4 (float4 units)
#define CH     512

typedef unsigned long long ull;

static __device__ float d_acc[GROUPS][NACC];   // pair sums + channel sums
static __device__ float d_Linv[GROUPS][NPAIR]; // packed lower-triangular Linv
static __device__ float d_bias[CH];            // Linv @ mean, per channel

// ---- packed f32x2 helpers (Blackwell) --------------------------------------
__device__ __forceinline__ void fma2(ull& d, ull a, ull b) {
    asm("fma.rn.f32x2 %0, %1, %2, %0;" : "+l"(d) : "l"(a), "l"(b));
}
__device__ __forceinline__ void add2(ull& d, ull a) {
    asm("add.rn.f32x2 %0, %0, %1;" : "+l"(d) : "l"(a));
}
__device__ __forceinline__ float unpack_add(ull v) {
    float lo, hi;
    asm("mov.b64 {%0,%1}, %2;" : "=f"(lo), "=f"(hi) : "l"(v));
    return lo + hi;
}
__device__ __forceinline__ ull pack2(float lo, float hi) {
    ull r;
    asm("mov.b64 %0, {%1,%2};" : "=l"(r) : "f"(lo), "f"(hi));
    return r;
}

struct V2 { ull a, b; };   // one float4 = two packed f32x2 halves

__device__ __forceinline__ V2 ld_v2(const float4* p) {
    const float4 f = __ldg(p);
    V2 v;
    v.a = pack2(f.x, f.y);
    v.b = pack2(f.z, f.w);
    return v;
}

// ---------------------------------------------------------------------------
__global__ void zero_kernel() {
    int i = blockIdx.x * blockDim.x + threadIdx.x;
    if (i < GROUPS * NACC) ((float*)d_acc)[i] = 0.f;
}

// ---------------------------------------------------------------------------
// Stats v10: role-per-BLOCK streaming, amp = 2.0x (410 MB), spill-free.
// grid = 1024 tiles x 4 roles, 256 threads, no smem staging, no sync in loop:
//   role 0: diag H0 (36 packed accs + 8 sums),  ch 0-7,  all positions
//   role 1: diag H1,                            ch 8-15, all positions
//   role 2: cross 8x8 (64 SCALAR float accs),   all ch,  positions [0,392)
//   role 3: cross 8x8,                          all ch,  positions [392,784)
// Cross role uses scalar accumulators: 64 acc + 64 load regs ~= 143 total
// (R11's packed version needed ~200+ -> no scheduling headroom / spill).
__global__ void __launch_bounds__(256) stats_kernel(const float* __restrict__ x) {
    const int role = blockIdx.x & 3;
    const int bg   = blockIdx.x >> 2;
    const int g = bg & 31;
    const int b = bg >> 5;
    const float4* in = (const float4*)(x + ((size_t)b * CH + (size_t)g * GS) * HW);

    const int tid  = threadIdx.x;
    const int lane = tid & 31;
    const int wid  = tid >> 5;

    if (role < 2) {
        // ---------------- diagonal half: 36 packed pairs + 8 packed sums ----
        const int co = role * 8;
        ull acc[36], sum[8];
#pragma unroll
        for (int k = 0; k < 36; k++) acc[k] = 0ull;
#pragma unroll
        for (int k = 0; k < 8; k++) sum[k] = 0ull;

        for (int pos = tid; pos < HW4; pos += 256) {
            V2 v[8];
#pragma unroll
            for (int c = 0; c < 8; c++) v[c] = ld_v2(in + (size_t)(co + c) * HW4 + pos);
#pragma unroll
            for (int i = 0; i < 8; i++) {
#pragma unroll
                for (int j = 0; j <= i; j++) {
                    const int k = i * (i + 1) / 2 + j;
                    fma2(acc[k], v[i].a, v[j].a);
                    fma2(acc[k], v[i].b, v[j].b);
                }
                add2(sum[i], v[i].a);
                add2(sum[i], v[i].b);
            }
        }

        float r[44];
#pragma unroll
        for (int k = 0; k < 36; k++) r[k] = unpack_add(acc[k]);
#pragma unroll
        for (int k = 0; k < 8; k++)  r[36 + k] = unpack_add(sum[k]);
#pragma unroll
        for (int k = 0; k < 44; k++) {
#pragma unroll
            for (int off = 16; off > 0; off >>= 1)
                r[k] += __shfl_xor_sync(0xffffffffu, r[k], off);
        }

        __shared__ float red[8][44];
        if (lane == 0) {
#pragma unroll
            for (int k = 0; k < 44; k++) red[wid][k] = r[k];
        }
        __syncthreads();
        if (tid < 44) {
            float s = 0.f;
#pragma unroll
            for (int w = 0; w < 8; w++) s += red[w][tid];
            if (tid < 36) {
                int i = 0;
                while ((i + 1) * (i + 2) / 2 <= tid) i++;
                const int j = tid - i * (i + 1) / 2;
                const int gi = co + i, gj = co + j;
                atomicAdd(&d_acc[g][gi * (gi + 1) / 2 + gj], s);
            } else {
                atomicAdd(&d_acc[g][NPAIR + co + (tid - 36)], s);
            }
        }
    } else {
        // ---------------- cross 8x8, scalar accumulators, half positions ----
        const int beg = (role - 2) * (HW4 / 2);
        const int end = beg + (HW4 / 2);
        float acc[64];
#pragma unroll
        for (int k = 0; k < 64; k++) acc[k] = 0.f;

        for (int pos = beg + tid; pos < end; pos += 256) {
            float4 u[8], w[8];
#pragma unroll
            for (int c = 0; c < 8; c++) {
                w[c] = __ldg(in + (size_t)c * HW4 + pos);
                u[c] = __ldg(in + (size_t)(8 + c) * HW4 + pos);
            }
#pragma unroll
            for (int i = 0; i < 8; i++)
#pragma unroll
                for (int j = 0; j < 8; j++) {
                    float a = acc[i * 8 + j];
                    a = fmaf(u[i].x, w[j].x, a);
                    a = fmaf(u[i].y, w[j].y, a);
                    a = fmaf(u[i].z, w[j].z, a);
                    a = fmaf(u[i].w, w[j].w, a);
                    acc[i * 8 + j] = a;
                }
        }

#pragma unroll
        for (int k = 0; k < 64; k++) {
#pragma unroll
            for (int off = 16; off > 0; off >>= 1)
                acc[k] += __shfl_xor_sync(0xffffffffu, acc[k], off);
        }

        __shared__ float red[8][64];
        if (lane == 0) {
#pragma unroll
            for (int k = 0; k < 64; k++) red[wid][k] = acc[k];
        }
        __syncthreads();
        if (tid < 64) {
            float s = 0.f;
#pragma unroll
            for (int w = 0; w < 8; w++) s += red[w][tid];
            const int i = tid >> 3, j = tid & 7;
            const int gi = 8 + i;
            atomicAdd(&d_acc[g][gi * (gi + 1) / 2 + j], s);
        }
    }
}

// ---------------------------------------------------------------------------
// Solve: one block per group, 16 threads, everything in shared memory, fp64.
__global__ void __launch_bounds__(16) solve_kernel() {
    const int g = blockIdx.x;
    const int t = threadIdx.x;
    __shared__ double P[GS][GS + 1];
    __shared__ double L[GS][GS + 1];
    __shared__ double V[GS][GS + 1];
    __shared__ double m[GS];

    const double Nd   = (double)BATCH * (double)HW;
    const double EPSd = 1e-3;
    const unsigned MASK = 0xffffu;

    m[t] = (double)d_acc[g][NPAIR + t] / Nd;
    __syncwarp(MASK);

    for (int j = 0; j < GS; j++) {
        const int i_ = t > j ? t : j, j_ = t > j ? j : t;
        double c = (double)d_acc[g][i_ * (i_ + 1) / 2 + j_] / Nd - m[t] * m[j];
        c *= (1.0 - EPSd);
        if (t == j) c += EPSd;
        P[t][j] = c;
    }
    __syncwarp(MASK);

    for (int j = 0; j < GS; j++) {
        if (t == j) {
            double s = P[j][j];
            for (int k = 0; k < j; k++) s -= L[j][k] * L[j][k];
            L[j][j] = sqrt(s);
        }
        __syncwarp(MASK);
        if (t > j) {
            double s = P[t][j];
            for (int k = 0; k < j; k++) s -= L[t][k] * L[j][k];
            L[t][j] = s / L[j][j];
        }
        __syncwarp(MASK);
    }

    V[t][t] = 1.0 / L[t][t];
    for (int i = t + 1; i < GS; i++) {
        double s = 0.0;
        for (int k = t; k < i; k++) s += L[i][k] * V[k][t];
        V[i][t] = -s / L[i][i];
    }
    __syncwarp(MASK);

    double bsum = 0.0;
    for (int j = 0; j <= t; j++) {
        d_Linv[g][t * (t + 1) / 2 + j] = (float)V[t][j];
        bsum += V[t][j] * m[j];
    }
    d_bias[g * GS + t] = (float)bsum;
}

// ---------------------------------------------------------------------------
// Apply (unchanged, proven ~66us / 68% DRAM):
// out_i = sum_{j<=i} Linv_ij * x_j - bias_i, float4, streaming stores.
__global__ void __launch_bounds__(256, 2) apply_kernel(const float* __restrict__ x,
                                                       float* __restrict__ out) {
    const int g = blockIdx.x & 31;
    const int b = blockIdx.x >> 5;

    __shared__ float Ls[NPAIR];
    __shared__ float bs[GS];
    if (threadIdx.x < NPAIR) Ls[threadIdx.x] = d_Linv[g][threadIdx.x];
    if (threadIdx.x < GS)    bs[threadIdx.x] = d_bias[g * GS + threadIdx.x];
    __syncthreads();

    const size_t off = ((size_t)b * CH + (size_t)g * GS) * HW;
    const float4* in = (const float4*)(x + off);
    float4*       op = (float4*)(out + off);

    for (int pos = threadIdx.x; pos < HW4; pos += 256) {
        float4 v[GS];
#pragma unroll
        for (int c = 0; c < GS; c++) v[c] = in[(size_t)c * HW4 + pos];
#pragma unroll
        for (int i = 0; i < GS; i++) {
            const float bias = bs[i];
            float4 a;
            a.x = -bias; a.y = -bias; a.z = -bias; a.w = -bias;
#pragma unroll
            for (int j = 0; j <= i; j++) {
                const float f = Ls[i * (i + 1) / 2 + j];
                a.x = fmaf(f, v[j].x, a.x);
                a.y = fmaf(f, v[j].y, a.y);
                a.z = fmaf(f, v[j].z, a.z);
                a.w = fmaf(f, v[j].w, a.w);
            }
            __stcs(&op[(size_t)i * HW4 + pos], a);
        }
    }
}

// ---------------------------------------------------------------------------
extern "C" void kernel_launch(void* const* d_in, const int* in_sizes, int n_in,
                              void* d_out, int out_size) {
    const float* x   = (const float*)d_in[0];
    float*       out = (float*)d_out;

    zero_kernel<<<(GROUPS * NACC + 255) / 256, 256>>>();
    stats_kernel<<<GROUPS * BATCH * 4, 256>>>(x);
    solve_kernel<<<GROUPS, 16>>>();
    apply_kernel<<<GROUPS * BATCH, 256>>>(x, out);
}

// round 13
// speedup vs baseline: 1.0270x; 1.0239x over previous
#include <cuda_runtime.h>
#include <cstdint>

#define GS     16
#define NPAIR  136          // 16*17/2 lower-triangular pairs
#define NACC   152          // 136 pair sums + 16 channel sums
#define GROUPS 32
#define BATCH  32
#define HW     3136         // 56*56
#define HW4    784          // HW/4 (float4 units)
#define CH     512

typedef unsigned long long ull;

static __device__ float d_acc[GROUPS][NACC];   // pair sums + channel sums
static __device__ float d_Linv[GROUPS][NPAIR]; // packed lower-triangular Linv
static __device__ float d_bias[CH];            // Linv @ mean, per channel

// ---- packed f32x2 helpers (Blackwell) --------------------------------------
__device__ __forceinline__ void fma2(ull& d, ull a, ull b) {
    asm("fma.rn.f32x2 %0, %1, %2, %0;" : "+l"(d) : "l"(a), "l"(b));
}
__device__ __forceinline__ void add2(ull& d, ull a) {
    asm("add.rn.f32x2 %0, %0, %1;" : "+l"(d) : "l"(a));
}
__device__ __forceinline__ float unpack_add(ull v) {
    float lo, hi;
    asm("mov.b64 {%0,%1}, %2;" : "=f"(lo), "=f"(hi) : "l"(v));
    return lo + hi;
}
__device__ __forceinline__ ull pack2(float lo, float hi) {
    ull r;
    asm("mov.b64 %0, {%1,%2};" : "=l"(r) : "f"(lo), "f"(hi));
    return r;
}

struct V2 { ull a, b; };   // one float4 = two packed f32x2 halves

__device__ __forceinline__ V2 ld_v2(const float4* p) {
    const float4 f = __ldg(p);
    V2 v;
    v.a = pack2(f.x, f.y);
    v.b = pack2(f.z, f.w);
    return v;
}

// ---------------------------------------------------------------------------
__global__ void zero_kernel() {
    int i = blockIdx.x * blockDim.x + threadIdx.x;
    if (i < GROUPS * NACC) ((float*)d_acc)[i] = 0.f;
}

// ---------------------------------------------------------------------------
// Stats v11: quad-block roles for HIGH OCCUPANCY (the measured constraint:
// R5 12 warps/SM beat R11 8 warps/SM despite more traffic -> latency-bound).
// grid = 1024 tiles x 10 roles, 256 threads, no smem staging, no loop sync:
//   roles 0-3: diag quad q (10 pairs + 4 sums, 14 packed accs, 4 loads/iter)
//   roles 4-9: cross quad-pair (16 pairs, 16 packed accs, 8 loads/iter)
// ~60-80 regs/thread -> 3 blocks/SM (24 warps) + prefetch headroom.
// L2 amp 4x (820MB ~ 68us at L2 cap), DRAM 1x via L2 reuse across roles.
__global__ void __launch_bounds__(256) stats_kernel(const float* __restrict__ x) {
    const int role = blockIdx.x % 10;
    const int bg   = blockIdx.x / 10;
    const int g = bg & 31;
    const int b = bg >> 5;
    const float4* in = (const float4*)(x + ((size_t)b * CH + (size_t)g * GS) * HW);

    const int tid  = threadIdx.x;
    const int lane = tid & 31;
    const int wid  = tid >> 5;

    __shared__ float red[8][16];

    if (role < 4) {
        // ---------------- diag quad: 10 packed pairs + 4 packed sums --------
        const int co = role * 4;
        ull acc[14];
#pragma unroll
        for (int k = 0; k < 14; k++) acc[k] = 0ull;

        for (int pos = tid; pos < HW4; pos += 256) {
            V2 v[4];
#pragma unroll
            for (int c = 0; c < 4; c++) v[c] = ld_v2(in + (size_t)(co + c) * HW4 + pos);
#pragma unroll
            for (int i = 0; i < 4; i++) {
#pragma unroll
                for (int j = 0; j <= i; j++) {
                    const int k = i * (i + 1) / 2 + j;
                    fma2(acc[k], v[i].a, v[j].a);
                    fma2(acc[k], v[i].b, v[j].b);
                }
                add2(acc[10 + i], v[i].a);
                add2(acc[10 + i], v[i].b);
            }
        }

        float r[14];
#pragma unroll
        for (int k = 0; k < 14; k++) r[k] = unpack_add(acc[k]);
#pragma unroll
        for (int k = 0; k < 14; k++) {
#pragma unroll
            for (int off = 16; off > 0; off >>= 1)
                r[k] += __shfl_xor_sync(0xffffffffu, r[k], off);
        }
        if (lane == 0) {
#pragma unroll
            for (int k = 0; k < 14; k++) red[wid][k] = r[k];
        }
        __syncthreads();
        if (tid < 14) {
            float s = 0.f;
#pragma unroll
            for (int w = 0; w < 8; w++) s += red[w][tid];
            if (tid < 10) {
                int i = 0;
                while ((i + 1) * (i + 2) / 2 <= tid) i++;
                const int j = tid - i * (i + 1) / 2;
                const int gi = co + i, gj = co + j;
                atomicAdd(&d_acc[g][gi * (gi + 1) / 2 + gj], s);
            } else {
                atomicAdd(&d_acc[g][NPAIR + co + (tid - 10)], s);
            }
        }
    } else {
        // ---------------- cross quad-pair: 16 packed pairs ------------------
        const int QI[6] = {1, 2, 3, 2, 3, 3};
        const int QJ[6] = {0, 0, 0, 1, 1, 2};
        const int qi = QI[role - 4], qj = QJ[role - 4];
        ull acc[16];
#pragma unroll
        for (int k = 0; k < 16; k++) acc[k] = 0ull;

        for (int pos = tid; pos < HW4; pos += 256) {
            V2 u[4], w[4];
#pragma unroll
            for (int c = 0; c < 4; c++) {
                u[c] = ld_v2(in + (size_t)(qi * 4 + c) * HW4 + pos);
                w[c] = ld_v2(in + (size_t)(qj * 4 + c) * HW4 + pos);
            }
#pragma unroll
            for (int i = 0; i < 4; i++)
#pragma unroll
                for (int j = 0; j < 4; j++) {
                    const int k = i * 4 + j;
                    fma2(acc[k], u[i].a, w[j].a);
                    fma2(acc[k], u[i].b, w[j].b);
                }
        }

        float r[16];
#pragma unroll
        for (int k = 0; k < 16; k++) r[k] = unpack_add(acc[k]);
#pragma unroll
        for (int k = 0; k < 16; k++) {
#pragma unroll
            for (int off = 16; off > 0; off >>= 1)
                r[k] += __shfl_xor_sync(0xffffffffu, r[k], off);
        }
        if (lane == 0) {
#pragma unroll
            for (int k = 0; k < 16; k++) red[wid][k] = r[k];
        }
        __syncthreads();
        if (tid < 16) {
            float s = 0.f;
#pragma unroll
            for (int w = 0; w < 8; w++) s += red[w][tid];
            const int gi = qi * 4 + (tid >> 2), gj = qj * 4 + (tid & 3);
            atomicAdd(&d_acc[g][gi * (gi + 1) / 2 + gj], s);
        }
    }
}

// ---------------------------------------------------------------------------
// Solve: one block per group, 16 threads, everything in shared memory, fp64.
__global__ void __launch_bounds__(16) solve_kernel() {
    const int g = blockIdx.x;
    const int t = threadIdx.x;
    __shared__ double P[GS][GS + 1];
    __shared__ double L[GS][GS + 1];
    __shared__ double V[GS][GS + 1];
    __shared__ double m[GS];

    const double Nd   = (double)BATCH * (double)HW;
    const double EPSd = 1e-3;
    const unsigned MASK = 0xffffu;

    m[t] = (double)d_acc[g][NPAIR + t] / Nd;
    __syncwarp(MASK);

    for (int j = 0; j < GS; j++) {
        const int i_ = t > j ? t : j, j_ = t > j ? j : t;
        double c = (double)d_acc[g][i_ * (i_ + 1) / 2 + j_] / Nd - m[t] * m[j];
        c *= (1.0 - EPSd);
        if (t == j) c += EPSd;
        P[t][j] = c;
    }
    __syncwarp(MASK);

    for (int j = 0; j < GS; j++) {
        if (t == j) {
            double s = P[j][j];
            for (int k = 0; k < j; k++) s -= L[j][k] * L[j][k];
            L[j][j] = sqrt(s);
        }
        __syncwarp(MASK);
        if (t > j) {
            double s = P[t][j];
            for (int k = 0; k < j; k++) s -= L[t][k] * L[j][k];
            L[t][j] = s / L[j][j];
        }
        __syncwarp(MASK);
    }

    V[t][t] = 1.0 / L[t][t];
    for (int i = t + 1; i < GS; i++) {
        double s = 0.0;
        for (int k = t; k < i; k++) s += L[i][k] * V[k][t];
        V[i][t] = -s / L[i][i];
    }
    __syncwarp(MASK);

    double bsum = 0.0;
    for (int j = 0; j <= t; j++) {
        d_Linv[g][t * (t + 1) / 2 + j] = (float)V[t][j];
        bsum += V[t][j] * m[j];
    }
    d_bias[g * GS + t] = (float)bsum;
}

// ---------------------------------------------------------------------------
// Apply (unchanged, proven ~66us / 68% DRAM):
// out_i = sum_{j<=i} Linv_ij * x_j - bias_i, float4, streaming stores.
__global__ void __launch_bounds__(256, 2) apply_kernel(const float* __restrict__ x,
                                                       float* __restrict__ out) {
    const int g = blockIdx.x & 31;
    const int b = blockIdx.x >> 5;

    __shared__ float Ls[NPAIR];
    __shared__ float bs[GS];
    if (threadIdx.x < NPAIR) Ls[threadIdx.x] = d_Linv[g][threadIdx.x];
    if (threadIdx.x < GS)    bs[threadIdx.x] = d_bias[g * GS + threadIdx.x];
    __syncthreads();

    const size_t off = ((size_t)b * CH + (size_t)g * GS) * HW;
    const float4* in = (const float4*)(x + off);
    float4*       op = (float4*)(out + off);

    for (int pos = threadIdx.x; pos < HW4; pos += 256) {
        float4 v[GS];
#pragma unroll
        for (int c = 0; c < GS; c++) v[c] = in[(size_t)c * HW4 + pos];
#pragma unroll
        for (int i = 0; i < GS; i++) {
            const float bias = bs[i];
            float4 a;
            a.x = -bias; a.y = -bias; a.z = -bias; a.w = -bias;
#pragma unroll
            for (int j = 0; j <= i; j++) {
                const float f = Ls[i * (i + 1) / 2 + j];
                a.x = fmaf(f, v[j].x, a.x);
                a.y = fmaf(f, v[j].y, a.y);
                a.z = fmaf(f, v[j].z, a.z);
                a.w = fmaf(f, v[j].w, a.w);
            }
            __stcs(&op[(size_t)i * HW4 + pos], a);
        }
    }
}

// ---------------------------------------------------------------------------
extern "C" void kernel_launch(void* const* d_in, const int* in_sizes, int n_in,
                              void* d_out, int out_size) {
    const float* x   = (const float*)d_in[0];
    float*       out = (float*)d_out;

    zero_kernel<<<(GROUPS * NACC + 255) / 256, 256>>>();
    stats_kernel<<<GROUPS * BATCH * 10, 256>>>(x);
    solve_kernel<<<GROUPS, 16>>>();
    apply_kernel<<<GROUPS * BATCH, 256>>>(x, out);
}

// round 14
// speedup vs baseline: 1.1164x; 1.0871x over previous
#include <cuda_runtime.h>
#include <cstdint>

#define GS     16
#define NPAIR  136          // 16*17/2 lower-triangular pairs
#define NACC   152          // 136 pair sums + 16 channel sums
#define GROUPS 32
#define BATCH  32
#define HW     3136         // 56*56
#define HW2    1568         // HW/2 (float2 units)
#define HW4    784          // HW/4 (float4 units)
#define CH     512

typedef unsigned long long ull;

static __device__ float d_acc[GROUPS][NACC];   // pair sums + channel sums
static __device__ float d_Linv[GROUPS][NPAIR]; // packed lower-triangular Linv
static __device__ float d_bias[CH];            // Linv @ mean, per channel

// ---- packed f32x2 helpers (Blackwell) --------------------------------------
__device__ __forceinline__ void fma2(ull& d, ull a, ull b) {
    asm("fma.rn.f32x2 %0, %1, %2, %0;" : "+l"(d) : "l"(a), "l"(b));
}
__device__ __forceinline__ void add2(ull& d, ull a) {
    asm("add.rn.f32x2 %0, %0, %1;" : "+l"(d) : "l"(a));
}
__device__ __forceinline__ float unpack_add(ull v) {
    float lo, hi;
    asm("mov.b64 {%0,%1}, %2;" : "=f"(lo), "=f"(hi) : "l"(v));
    return lo + hi;
}

// ---------------------------------------------------------------------------
__global__ void zero_kernel() {
    int i = blockIdx.x * blockDim.x + threadIdx.x;
    if (i < GROUPS * NACC) ((float*)d_acc)[i] = 0.f;
}

// ---------------------------------------------------------------------------
// Stats v12: amp 2.0 (410 MB) AND 16 warps/SM together.
// Measured law (R5/R11/R12/R13/apply): streaming BW ~= f(warps/SM), saturating
// ~6.2 TB/s at >=16 warps; runtime = traffic / BW. So every role must fit
// 2 blocks/SM: __launch_bounds__(256,2) (128-reg cap) with per-role budgets:
//   role 0: diag ch0-7,  all float2 positions. 44 packed accs(88) + 8 ull
//           loads(16) ~= 114 regs.
//   role 1: diag ch8-15, same.
//   role 2: cross 8x8, positions [0, HW2/2). 64 SCALAR accs(64) + 16 float2
//           loads(32) ~= 106 regs.
//   role 3: cross 8x8, positions [HW2/2, HW2).
// No smem staging, no loop sync (the family that never deadlocked).
__global__ void __launch_bounds__(256, 2) stats_kernel(const float* __restrict__ x) {
    const int role = blockIdx.x & 3;
    const int bg   = blockIdx.x >> 2;
    const int g = bg & 31;
    const int b = bg >> 5;
    const float* base = x + ((size_t)b * CH + (size_t)g * GS) * HW;

    const int tid  = threadIdx.x;
    const int lane = tid & 31;
    const int wid  = tid >> 5;

    if (role < 2) {
        // ---------------- diagonal half: packed accs, ull (float2) loads ----
        const int co = role * 8;
        const ull* in = (const ull*)base + (size_t)co * HW2;
        ull acc[36], sum[8];
#pragma unroll
        for (int k = 0; k < 36; k++) acc[k] = 0ull;
#pragma unroll
        for (int k = 0; k < 8; k++) sum[k] = 0ull;

        for (int pos = tid; pos < HW2; pos += 256) {
            ull v[8];
#pragma unroll
            for (int c = 0; c < 8; c++) v[c] = __ldg(in + (size_t)c * HW2 + pos);
#pragma unroll
            for (int i = 0; i < 8; i++) {
#pragma unroll
                for (int j = 0; j <= i; j++)
                    fma2(acc[i * (i + 1) / 2 + j], v[i], v[j]);
                add2(sum[i], v[i]);
            }
        }

        float r[44];
#pragma unroll
        for (int k = 0; k < 36; k++) r[k] = unpack_add(acc[k]);
#pragma unroll
        for (int k = 0; k < 8; k++)  r[36 + k] = unpack_add(sum[k]);
#pragma unroll
        for (int k = 0; k < 44; k++) {
#pragma unroll
            for (int off = 16; off > 0; off >>= 1)
                r[k] += __shfl_xor_sync(0xffffffffu, r[k], off);
        }

        __shared__ float red[8][44];
        if (lane == 0) {
#pragma unroll
            for (int k = 0; k < 44; k++) red[wid][k] = r[k];
        }
        __syncthreads();
        if (tid < 44) {
            float s = 0.f;
#pragma unroll
            for (int w = 0; w < 8; w++) s += red[w][tid];
            if (tid < 36) {
                int i = 0;
                while ((i + 1) * (i + 2) / 2 <= tid) i++;
                const int j = tid - i * (i + 1) / 2;
                const int gi = co + i, gj = co + j;
                atomicAdd(&d_acc[g][gi * (gi + 1) / 2 + gj], s);
            } else {
                atomicAdd(&d_acc[g][NPAIR + co + (tid - 36)], s);
            }
        }
    } else {
        // ------------- cross 8x8: scalar accs, float2 loads, half positions -
        const float2* in = (const float2*)base;
        const int beg = (role - 2) * (HW2 / 2);
        const int end = beg + (HW2 / 2);
        float acc[64];
#pragma unroll
        for (int k = 0; k < 64; k++) acc[k] = 0.f;

        for (int pos = beg + tid; pos < end; pos += 256) {
            float2 u[8], w[8];
#pragma unroll
            for (int c = 0; c < 8; c++) {
                w[c] = __ldg(in + (size_t)c * HW2 + pos);
                u[c] = __ldg(in + (size_t)(8 + c) * HW2 + pos);
            }
#pragma unroll
            for (int i = 0; i < 8; i++)
#pragma unroll
                for (int j = 0; j < 8; j++) {
                    float a = acc[i * 8 + j];
                    a = fmaf(u[i].x, w[j].x, a);
                    a = fmaf(u[i].y, w[j].y, a);
                    acc[i * 8 + j] = a;
                }
        }

#pragma unroll
        for (int k = 0; k < 64; k++) {
#pragma unroll
            for (int off = 16; off > 0; off >>= 1)
                acc[k] += __shfl_xor_sync(0xffffffffu, acc[k], off);
        }

        __shared__ float red[8][64];
        if (lane == 0) {
#pragma unroll
            for (int k = 0; k < 64; k++) red[wid][k] = acc[k];
        }
        __syncthreads();
        if (tid < 64) {
            float s = 0.f;
#pragma unroll
            for (int w = 0; w < 8; w++) s += red[w][tid];
            const int i = tid >> 3, j = tid & 7;
            const int gi = 8 + i;
            atomicAdd(&d_acc[g][gi * (gi + 1) / 2 + j], s);
        }
    }
}

// ---------------------------------------------------------------------------
// Solve: one block per group, 16 threads, everything in shared memory, fp64.
__global__ void __launch_bounds__(16) solve_kernel() {
    const int g = blockIdx.x;
    const int t = threadIdx.x;
    __shared__ double P[GS][GS + 1];
    __shared__ double L[GS][GS + 1];
    __shared__ double V[GS][GS + 1];
    __shared__ double m[GS];

    const double Nd   = (double)BATCH * (double)HW;
    const double EPSd = 1e-3;
    const unsigned MASK = 0xffffu;

    m[t] = (double)d_acc[g][NPAIR + t] / Nd;
    __syncwarp(MASK);

    for (int j = 0; j < GS; j++) {
        const int i_ = t > j ? t : j, j_ = t > j ? j : t;
        double c = (double)d_acc[g][i_ * (i_ + 1) / 2 + j_] / Nd - m[t] * m[j];
        c *= (1.0 - EPSd);
        if (t == j) c += EPSd;
        P[t][j] = c;
    }
    __syncwarp(MASK);

    for (int j = 0; j < GS; j++) {
        if (t == j) {
            double s = P[j][j];
            for (int k = 0; k < j; k++) s -= L[j][k] * L[j][k];
            L[j][j] = sqrt(s);
        }
        __syncwarp(MASK);
        if (t > j) {
            double s = P[t][j];
            for (int k = 0; k < j; k++) s -= L[t][k] * L[j][k];
            L[t][j] = s / L[j][j];
        }
        __syncwarp(MASK);
    }

    V[t][t] = 1.0 / L[t][t];
    for (int i = t + 1; i < GS; i++) {
        double s = 0.0;
        for (int k = t; k < i; k++) s += L[i][k] * V[k][t];
        V[i][t] = -s / L[i][i];
    }
    __syncwarp(MASK);

    double bsum = 0.0;
    for (int j = 0; j <= t; j++) {
        d_Linv[g][t * (t + 1) / 2 + j] = (float)V[t][j];
        bsum += V[t][j] * m[j];
    }
    d_bias[g * GS + t] = (float)bsum;
}

// ---------------------------------------------------------------------------
// Apply (unchanged, proven ~66us / 68% DRAM):
// out_i = sum_{j<=i} Linv_ij * x_j - bias_i, float4, streaming stores.
__global__ void __launch_bounds__(256, 2) apply_kernel(const float* __restrict__ x,
                                                       float* __restrict__ out) {
    const int g = blockIdx.x & 31;
    const int b = blockIdx.x >> 5;

    __shared__ float Ls[NPAIR];
    __shared__ float bs[GS];
    if (threadIdx.x < NPAIR) Ls[threadIdx.x] = d_Linv[g][threadIdx.x];
    if (threadIdx.x < GS)    bs[threadIdx.x] = d_bias[g * GS + threadIdx.x];
    __syncthreads();

    const size_t off = ((size_t)b * CH + (size_t)g * GS) * HW;
    const float4* in = (const float4*)(x + off);
    float4*       op = (float4*)(out + off);

    for (int pos = threadIdx.x; pos < HW4; pos += 256) {
        float4 v[GS];
#pragma unroll
        for (int c = 0; c < GS; c++) v[c] = in[(size_t)c * HW4 + pos];
#pragma unroll
        for (int i = 0; i < GS; i++) {
            const float bias = bs[i];
            float4 a;
            a.x = -bias; a.y = -bias; a.z = -bias; a.w = -bias;
#pragma unroll
            for (int j = 0; j <= i; j++) {
                const float f = Ls[i * (i + 1) / 2 + j];
                a.x = fmaf(f, v[j].x, a.x);
                a.y = fmaf(f, v[j].y, a.y);
                a.z = fmaf(f, v[j].z, a.z);
                a.w = fmaf(f, v[j].w, a.w);
            }
            __stcs(&op[(size_t)i * HW4 + pos], a);
        }
    }
}

// ---------------------------------------------------------------------------
extern "C" void kernel_launch(void* const* d_in, const int* in_sizes, int n_in,
                              void* d_out, int out_size) {
    const float* x   = (const float*)d_in[0];
    float*       out = (float*)d_out;

    zero_kernel<<<(GROUPS * NACC + 255) / 256, 256>>>();
    stats_kernel<<<GROUPS * BATCH * 4, 256>>>(x);
    solve_kernel<<<GROUPS, 16>>>();
    apply_kernel<<<GROUPS * BATCH, 256>>>(x, out);
}